// round 16
// baseline (speedup 1.0000x reference)
#include <cuda_runtime.h>
#include <cuda_fp16.h>
#include <math.h>
#include <stdint.h>

// ---------------------------------------------------------------------------
// Problem constants
// ---------------------------------------------------------------------------
#define B_     4
#define NTOK   8192
#define MTOK   1024
#define DMODEL 1024
#define H_     16
#define DH     64
#define EPSF   1e-6f
#define NCHUNK 9               // 9216 / 1024

// ---------------------------------------------------------------------------
// Scratch (static device globals; no allocation allowed)
// ---------------------------------------------------------------------------
__device__ __half g_qkv [(size_t)B_ * NTOK * 3 * DMODEL];   // fp16 intermediates
__device__ __half g_ckv [(size_t)B_ * MTOK * 2 * DMODEL];
__device__ float  g_kvp [(size_t)NCHUNK * 64 * DH * DH];
__device__ float  g_ksp [(size_t)NCHUNK * 64 * DH];
__device__ float  g_kv  [64 * DH * DH];
__device__ float  g_ksum[64 * DH];
__device__ __half g_ah  [(size_t)B_ * NTOK * DMODEL];
__device__ __half g_yh  [(size_t)B_ * MTOK * DMODEL];
__device__ __half g_wh  [(size_t)6 * DMODEL * DMODEL];  // qkv(3M)+ckv(2M)+out(1M)

// ---------------------------------------------------------------------------
// PTX helpers (sm_80-compatible: cp.async, ldmatrix, mma.sync)
// ---------------------------------------------------------------------------
__device__ __forceinline__ uint32_t smem_u32(const void* p) {
    uint32_t a;
    asm("{ .reg .u64 t; cvta.to.shared.u64 t, %1; cvt.u32.u64 %0, t; }"
        : "=r"(a) : "l"(p));
    return a;
}
__device__ __forceinline__ void cp16(uint32_t s, const void* g) {
    asm volatile("cp.async.cg.shared.global [%0], [%1], 16;" :: "r"(s), "l"(g));
}
#define CP_COMMIT() asm volatile("cp.async.commit_group;" ::: "memory")
#define CP_WAIT2()  asm volatile("cp.async.wait_group 2;" ::: "memory")

__device__ __forceinline__ void ldsm_x4(uint32_t& r0, uint32_t& r1,
                                        uint32_t& r2, uint32_t& r3, uint32_t addr) {
    asm volatile("ldmatrix.sync.aligned.m8n8.x4.shared.b16 {%0,%1,%2,%3}, [%4];"
                 : "=r"(r0), "=r"(r1), "=r"(r2), "=r"(r3) : "r"(addr));
}
__device__ __forceinline__ void mma_f16(float* c, const uint32_t* a, const uint32_t* b) {
    asm volatile(
        "mma.sync.aligned.m16n8k16.row.col.f32.f16.f16.f32 "
        "{%0,%1,%2,%3}, {%4,%5,%6,%7}, {%8,%9}, {%0,%1,%2,%3};"
        : "+f"(c[0]), "+f"(c[1]), "+f"(c[2]), "+f"(c[3])
        : "r"(a[0]), "r"(a[1]), "r"(a[2]), "r"(a[3]), "r"(b[0]), "r"(b[1]));
}

// ---------------------------------------------------------------------------
// Convert fp32 -> fp16 (elementwise, float4 per thread)
// ---------------------------------------------------------------------------
__global__ void __launch_bounds__(256) conv_h(
    const float* __restrict__ in, __half* __restrict__ hi, int n4)
{
    const int i = blockIdx.x * blockDim.x + threadIdx.x;
    if (i >= n4) return;
    const float4 v = reinterpret_cast<const float4*>(in)[i];
    reinterpret_cast<__half2*>(hi)[2 * i]     = __halves2half2(__float2half(v.x), __float2half(v.y));
    reinterpret_cast<__half2*>(hi)[2 * i + 1] = __halves2half2(__float2half(v.z), __float2half(v.w));
}

// ---------------------------------------------------------------------------
// Transpose weights: w[1024, C] fp32 -> t[C, 1024] fp16
// ---------------------------------------------------------------------------
__global__ void __launch_bounds__(256) conv_w_t(
    const float* __restrict__ w, __half* __restrict__ th, int C)
{
    __shared__ float s[32][33];
    const int c0 = blockIdx.x * 32;
    const int k0 = blockIdx.y * 32;
    const int tx = threadIdx.x;
    const int ty = threadIdx.y;
#pragma unroll
    for (int i = 0; i < 32; i += 8)
        s[ty + i][tx] = w[(size_t)(k0 + ty + i) * C + c0 + tx];
    __syncthreads();
#pragma unroll
    for (int i = 0; i < 32; i += 8)
        th[(size_t)(c0 + ty + i) * DMODEL + k0 + tx] = __float2half(s[tx][ty + i]);
}

// ---------------------------------------------------------------------------
// Shared GEMM mainloop (128x128 tile, BK=32, 8 warps 2x4, 64x32/warp)
// 4-stage cp.async pipeline, ONE __syncthreads per iteration.
// All 12 ldsm for BOTH ks halves issued before the 32 MMAs so the second
// half's fragment-load latency hides under the first half's MMA stream
// (asm volatile pins SASS order — this batching must be done by hand).
// ---------------------------------------------------------------------------
#define BM  128
#define BN  128
#define ROWB 80                       // 64B data + 16B pad
#define OFF_A 0
#define OFF_B 10240
#define STAGE 20480
#define NST   4
#define GEMM_SMEM (NST * STAGE)       // 81920 (also covers epi 68608)
#define CSTRIDE 132

// Pipeline invariants: stages kt..kt+2 in flight at loop head (3 groups);
// wait_group 2 completes stage kt. Load at iter kt targets buffer (kt+3)&3
// = (kt-1)&3, whose compute finished before this iteration's barrier.
// Empty commit groups keep the outstanding-count arithmetic exact.
#define GEMM_MAINLOOP(accvar)                                                   \
    load_tile(0, 0); CP_COMMIT();                                               \
    load_tile(1, 1); CP_COMMIT();                                               \
    load_tile(2, 2); CP_COMMIT();                                               \
    for (int kt = 0; kt < 32; kt++) {                                           \
        CP_WAIT2();                                                             \
        __syncthreads();                                                        \
        if (kt + 3 < 32) load_tile((kt + 3) & 3, kt + 3);                       \
        CP_COMMIT();                                                            \
        const uint32_t base = sb + (kt & 3) * STAGE;                            \
        uint32_t af[2][4][4], bf[2][4][2];                                      \
        _Pragma("unroll")                                                       \
        for (int ks = 0; ks < 2; ks++) {                                        \
            _Pragma("unroll")                                                   \
            for (int mt = 0; mt < 4; mt++)                                      \
                ldsm_x4(af[ks][mt][0], af[ks][mt][1], af[ks][mt][2], af[ks][mt][3], \
                        base + OFF_A + (aRow + mt * 16) * ROWB + ks * 32 + aCol); \
            _Pragma("unroll")                                                   \
            for (int p = 0; p < 2; p++) {                                       \
                uint32_t t0, t1, t2, t3;                                        \
                ldsm_x4(t0, t1, t2, t3,                                         \
                        base + OFF_B + (bRow + p * 16) * ROWB + ks * 32 + bCol);\
                bf[ks][p * 2][0] = t0; bf[ks][p * 2][1] = t1;                   \
                bf[ks][p * 2 + 1][0] = t2; bf[ks][p * 2 + 1][1] = t3;           \
            }                                                                   \
        }                                                                       \
        _Pragma("unroll")                                                       \
        for (int ks = 0; ks < 2; ks++)                                          \
            _Pragma("unroll")                                                   \
            for (int mt = 0; mt < 4; mt++)                                      \
                _Pragma("unroll")                                               \
                for (int nt = 0; nt < 4; nt++)                                  \
                    mma_f16(accvar[mt][nt], af[ks][mt], bf[ks][nt]);            \
    }

// ---------------------------------------------------------------------------
// GEMM variant H: fp16 output, staged epilogue with fused RMSNorm+ReLU
// ---------------------------------------------------------------------------
__global__ void __launch_bounds__(256, 2) gemm_mma_h(
    const __half* __restrict__ Ah, const __half* __restrict__ Bh,
    const float* __restrict__ bias, __half* __restrict__ C, int Nd,
    int nlimit, const float* __restrict__ wq, const float* __restrict__ wk)
{
    extern __shared__ char smem[];
    const uint32_t sb = smem_u32(smem);
    const int tid  = threadIdx.x;
    const int wid  = tid >> 5;
    const int lane = tid & 31;
    const int m0 = blockIdx.y * BM;
    const int n0 = blockIdx.x * BN;

    const __half* gA = Ah + (size_t)m0 * 1024;
    const __half* gB = Bh + (size_t)n0 * 1024;

    const int lr = tid >> 1;
    const int lc = (tid & 1) * 2;

    auto load_tile = [&](int buf, int kt) {
        const uint32_t s0 = sb + buf * STAGE + lr * ROWB + lc * 16;
        const size_t   go = (size_t)lr * 1024 + kt * 32 + lc * 8;
        cp16(s0 + OFF_A,      gA + go);
        cp16(s0 + OFF_A + 16, gA + go + 8);
        cp16(s0 + OFF_B,      gB + go);
        cp16(s0 + OFF_B + 16, gB + go + 8);
    };

    const int mbase = (wid >> 2) * 64;
    const int nbase = (wid & 3) * 32;
    const int aRow = mbase + (lane & 15);
    const int aCol = (lane >> 4) * 16;
    const int bRow = nbase + ((lane >> 4) << 3) + (lane & 7);
    const int bCol = ((lane >> 3) & 1) * 16;

    float acc[4][4][4];
#pragma unroll
    for (int i = 0; i < 4; i++)
#pragma unroll
        for (int j = 0; j < 4; j++)
#pragma unroll
            for (int k = 0; k < 4; k++) acc[i][j][k] = 0.0f;

    GEMM_MAINLOOP(acc)

    // ---- Epilogue: stage (acc+bias) to smem, fused RMSNorm+ReLU, fp16 store
    __syncthreads();
    float* cs = (float*)smem;
    float* sc = cs + 128 * CSTRIDE;
    {
        const int erow = lane >> 2;
        const int ecol = (lane & 3) * 2;
#pragma unroll
        for (int nt = 0; nt < 4; nt++) {
            const int col = nbase + nt * 8 + ecol;
            const float bx = bias[n0 + col], by = bias[n0 + col + 1];
#pragma unroll
            for (int mt = 0; mt < 4; mt++) {
                const int r0 = mbase + mt * 16 + erow;
                cs[r0 * CSTRIDE + col]           = acc[mt][nt][0] + bx;
                cs[r0 * CSTRIDE + col + 1]       = acc[mt][nt][1] + by;
                cs[(r0 + 8) * CSTRIDE + col]     = acc[mt][nt][2] + bx;
                cs[(r0 + 8) * CSTRIDE + col + 1] = acc[mt][nt][3] + by;
            }
        }
    }
    __syncthreads();

    const bool donorm = (n0 < nlimit);
    if (donorm) {
        const int row  = tid >> 1;
        const int head = tid & 1;
        const float* rp = cs + row * CSTRIDE + head * 64;
        float ss = 0.0f;
#pragma unroll
        for (int j = 0; j < 64; j += 4) {
            float4 v = *(const float4*)(rp + j);
            ss += v.x * v.x + v.y * v.y + v.z * v.z + v.w * v.w;
        }
        sc[tid] = rsqrtf(ss * (1.0f / 64.0f) + EPSF);
        __syncthreads();
    }

    const float* wv = (n0 < 1024) ? wq : wk;
#pragma unroll
    for (int i = 0; i < 16; i++) {
        const int idx = i * 256 + tid;
        const int row = idx >> 5;
        const int c4  = (idx & 31) * 4;
        float4 v = *(float4*)(cs + row * CSTRIDE + c4);
        if (donorm) {
            const float s = sc[row * 2 + (c4 >> 6)];
            const float4 w4 = *(const float4*)(wv + (c4 & 63));
            v.x = fmaxf(v.x * s * w4.x, 0.0f);
            v.y = fmaxf(v.y * s * w4.y, 0.0f);
            v.z = fmaxf(v.z * s * w4.z, 0.0f);
            v.w = fmaxf(v.w * s * w4.w, 0.0f);
        }
        const __half2 h01 = __halves2half2(__float2half(v.x), __float2half(v.y));
        const __half2 h23 = __halves2half2(__float2half(v.z), __float2half(v.w));
        uint2 pk;
        pk.x = *(const uint32_t*)&h01;
        pk.y = *(const uint32_t*)&h23;
        *(uint2*)(C + (size_t)(m0 + row) * Nd + n0 + c4) = pk;
    }
}

// ---------------------------------------------------------------------------
// GEMM variant F: fp32 output, direct-store epilogue (no norm, no staging)
// ---------------------------------------------------------------------------
__global__ void __launch_bounds__(256, 2) gemm_mma_f(
    const __half* __restrict__ Ah, const __half* __restrict__ Bh,
    const float* __restrict__ bias, float* __restrict__ C, int Nd)
{
    extern __shared__ char smem[];
    const uint32_t sb = smem_u32(smem);
    const int tid  = threadIdx.x;
    const int wid  = tid >> 5;
    const int lane = tid & 31;
    const int m0 = blockIdx.y * BM;
    const int n0 = blockIdx.x * BN;

    const __half* gA = Ah + (size_t)m0 * 1024;
    const __half* gB = Bh + (size_t)n0 * 1024;

    const int lr = tid >> 1;
    const int lc = (tid & 1) * 2;

    auto load_tile = [&](int buf, int kt) {
        const uint32_t s0 = sb + buf * STAGE + lr * ROWB + lc * 16;
        const size_t   go = (size_t)lr * 1024 + kt * 32 + lc * 8;
        cp16(s0 + OFF_A,      gA + go);
        cp16(s0 + OFF_A + 16, gA + go + 8);
        cp16(s0 + OFF_B,      gB + go);
        cp16(s0 + OFF_B + 16, gB + go + 8);
    };

    const int mbase = (wid >> 2) * 64;
    const int nbase = (wid & 3) * 32;
    const int aRow = mbase + (lane & 15);
    const int aCol = (lane >> 4) * 16;
    const int bRow = nbase + ((lane >> 4) << 3) + (lane & 7);
    const int bCol = ((lane >> 3) & 1) * 16;

    float acc[4][4][4];
#pragma unroll
    for (int i = 0; i < 4; i++)
#pragma unroll
        for (int j = 0; j < 4; j++)
#pragma unroll
            for (int k = 0; k < 4; k++) acc[i][j][k] = 0.0f;

    GEMM_MAINLOOP(acc)

    // direct stores (32B-sector coalesced per 4-lane group)
    const int erow = lane >> 2;
    const int ecol = (lane & 3) * 2;
#pragma unroll
    for (int mt = 0; mt < 4; mt++)
#pragma unroll
        for (int nt = 0; nt < 4; nt++) {
            const int col = n0 + nbase + nt * 8 + ecol;
            const float bx = bias[col], by = bias[col + 1];
            const int row0 = m0 + mbase + mt * 16 + erow;
            float2 v0 = make_float2(acc[mt][nt][0] + bx, acc[mt][nt][1] + by);
            float2 v1 = make_float2(acc[mt][nt][2] + bx, acc[mt][nt][3] + by);
            *(float2*)(C + (size_t)row0 * Nd + col)       = v0;
            *(float2*)(C + (size_t)(row0 + 8) * Nd + col) = v1;
        }
}

// ---------------------------------------------------------------------------
// kv[b,h,d,e] = sum_s k[s,d] v[s,e];  ksum[b,h,d] = sum_s k[s,d]
// fp16 inputs, fp32 accumulation, chunked partials (deterministic)
// ---------------------------------------------------------------------------
#define SCHUNK 1024
#define SSUB   16

__global__ void kv_accum(const __half* __restrict__ qkv, const __half* __restrict__ ckv,
                         float* __restrict__ kvp, float* __restrict__ ksp)
{
    const int bh = blockIdx.y;
    const int b  = bh >> 4;
    const int h  = bh & 15;
    const int s0 = blockIdx.x * SCHUNK;

    __shared__ float sk[SSUB][DH];
    __shared__ float sv[SSUB][DH];

    const int tid = threadIdx.x;
    const int d   = tid >> 2;
    const int eg  = tid & 3;
    const int lsi = tid >> 4;          // 0..15
    const int ldd = (tid & 15) * 4;    // 0..60

    float acc[16];
#pragma unroll
    for (int j = 0; j < 16; j++) acc[j] = 0.0f;
    float ksl = 0.0f;

    for (int st = s0; st < s0 + SCHUNK; st += SSUB) {
        {
            const int s = st + lsi;
            const __half *rk, *rv;
            if (s < NTOK) {
                const __half* row = qkv + (size_t)(b * NTOK + s) * (3 * DMODEL);
                rk = row + DMODEL + h * DH + ldd;
                rv = row + 2 * DMODEL + h * DH + ldd;
            } else {
                const __half* row = ckv + (size_t)(b * MTOK + (s - NTOK)) * (2 * DMODEL);
                rk = row + h * DH + ldd;
                rv = row + DMODEL + h * DH + ldd;
            }
            const __half2 k01 = *(const __half2*)(rk);
            const __half2 k23 = *(const __half2*)(rk + 2);
            const __half2 v01 = *(const __half2*)(rv);
            const __half2 v23 = *(const __half2*)(rv + 2);
            const float2 fk01 = __half22float2(k01), fk23 = __half22float2(k23);
            const float2 fv01 = __half22float2(v01), fv23 = __half22float2(v23);
            sk[lsi][ldd]     = fk01.x; sk[lsi][ldd + 1] = fk01.y;
            sk[lsi][ldd + 2] = fk23.x; sk[lsi][ldd + 3] = fk23.y;
            sv[lsi][ldd]     = fv01.x; sv[lsi][ldd + 1] = fv01.y;
            sv[lsi][ldd + 2] = fv23.x; sv[lsi][ldd + 3] = fv23.y;
        }
        __syncthreads();
#pragma unroll
        for (int si = 0; si < SSUB; si++) {
            const float kd = sk[si][d];
            if (eg == 0) ksl += kd;
#pragma unroll
            for (int j = 0; j < 16; j++)
                acc[j] = fmaf(kd, sv[si][eg * 16 + j], acc[j]);
        }
        __syncthreads();
    }

    float* kvpp = kvp + (size_t)blockIdx.x * 64 * DH * DH + (size_t)bh * DH * DH + d * DH + eg * 16;
#pragma unroll
    for (int j = 0; j < 16; j++) kvpp[j] = acc[j];
    if (eg == 0) ksp[(size_t)blockIdx.x * 64 * DH + bh * DH + d] = ksl;
}

__global__ void kv_reduce(const float* __restrict__ kvp, const float* __restrict__ ksp,
                          float* __restrict__ kv, float* __restrict__ ksum)
{
    const int idx = blockIdx.x * blockDim.x + threadIdx.x;
    if (idx < 64 * DH * DH) {
        float s = 0.0f;
#pragma unroll
        for (int c = 0; c < NCHUNK; c++) s += kvp[(size_t)c * 64 * DH * DH + idx];
        kv[idx] = s;
    }
    if (idx < 64 * DH) {
        float s = 0.0f;
#pragma unroll
        for (int c = 0; c < NCHUNK; c++) s += ksp[(size_t)c * 64 * DH + idx];
        ksum[idx] = s;
    }
}

// ---------------------------------------------------------------------------
// attn = (q @ kv) / (q . ksum + eps); fp16 q in, fp16 out
// ---------------------------------------------------------------------------
__global__ void attn_apply(const __half* __restrict__ qkv, const float* __restrict__ kv,
                           const float* __restrict__ ksum, __half* __restrict__ oh)
{
    const int bh = blockIdx.y;
    const int b  = bh >> 4;
    const int h  = bh & 15;

    __shared__ float skv[DH * DH];
    __shared__ float sks[DH];

    const int tid = threadIdx.x;
    for (int i = tid; i < DH * DH; i += 256) skv[i] = kv[(size_t)bh * DH * DH + i];
    if (tid < DH) sks[tid] = ksum[bh * DH + tid];
    __syncthreads();

    const int warp = tid >> 5;
    const int lane = tid & 31;
    const int t0   = blockIdx.x * 64 + warp * 8;

    for (int i = 0; i < 8; i++) {
        const int t = t0 + i;
        const __half* qp = qkv + (size_t)(b * NTOK + t) * (3 * DMODEL) + h * DH;
        const float q0 = __half2float(qp[lane]);
        const float q1 = __half2float(qp[lane + 32]);

        float sc = q0 * sks[lane] + q1 * sks[lane + 32];
#pragma unroll
        for (int o = 16; o > 0; o >>= 1) sc += __shfl_xor_sync(0xffffffffu, sc, o);
        const float inv = 1.0f / (sc + EPSF);

        float a0 = 0.0f, a1 = 0.0f;
#pragma unroll
        for (int d = 0; d < 32; d++) {
            const float qd = __shfl_sync(0xffffffffu, q0, d);
            a0 = fmaf(qd, skv[d * DH + lane], a0);
            a1 = fmaf(qd, skv[d * DH + lane + 32], a1);
        }
#pragma unroll
        for (int d = 0; d < 32; d++) {
            const float qd = __shfl_sync(0xffffffffu, q1, d);
            a0 = fmaf(qd, skv[(d + 32) * DH + lane], a0);
            a1 = fmaf(qd, skv[(d + 32) * DH + lane + 32], a1);
        }

        const size_t o0 = (size_t)(b * NTOK + t) * DMODEL + h * DH;
        oh[o0 + lane]      = __float2half(a0 * inv);
        oh[o0 + lane + 32] = __float2half(a1 * inv);
    }
}

// ---------------------------------------------------------------------------
// Launch — QKV GEMM at my idx 3 (ncu capture slot)
// ---------------------------------------------------------------------------
extern "C" void kernel_launch(void* const* d_in, const int* in_sizes, int n_in,
                              void* d_out, int out_size)
{
    const float* x     = (const float*)d_in[0];
    const float* y     = (const float*)d_in[1];
    const float* w_qkv = (const float*)d_in[2];
    const float* b_qkv = (const float*)d_in[3];
    const float* w_ckv = (const float*)d_in[4];
    const float* b_ckv = (const float*)d_in[5];
    const float* w_out = (const float*)d_in[6];
    const float* b_out = (const float*)d_in[7];
    const float* qn_w  = (const float*)d_in[8];
    const float* kn_w  = (const float*)d_in[9];
    const float* ckn_w = (const float*)d_in[10];
    float* out = (float*)d_out;

    float *p_kvp, *p_ksp, *p_kv, *p_ksum;
    __half *p_qkv, *p_ckv, *p_ah, *p_yh, *p_wh;
    cudaGetSymbolAddress((void**)&p_qkv,  g_qkv);
    cudaGetSymbolAddress((void**)&p_ckv,  g_ckv);
    cudaGetSymbolAddress((void**)&p_kvp,  g_kvp);
    cudaGetSymbolAddress((void**)&p_ksp,  g_ksp);
    cudaGetSymbolAddress((void**)&p_kv,   g_kv);
    cudaGetSymbolAddress((void**)&p_ksum, g_ksum);
    cudaGetSymbolAddress((void**)&p_ah,   g_ah);
    cudaGetSymbolAddress((void**)&p_yh,   g_yh);
    cudaGetSymbolAddress((void**)&p_wh,   g_wh);

    // weight regions: [0,3M) qkv, [3M,5M) ckv, [5M,6M) out
    const size_t W_QKV = 0;
    const size_t W_CKV = (size_t)3 * DMODEL * DMODEL;
    const size_t W_OUT = (size_t)5 * DMODEL * DMODEL;

    cudaFuncSetAttribute(gemm_mma_h, cudaFuncAttributeMaxDynamicSharedMemorySize, GEMM_SMEM);
    cudaFuncSetAttribute(gemm_mma_f, cudaFuncAttributeMaxDynamicSharedMemorySize, GEMM_SMEM);

    const dim3 blk(256);
    const dim3 wblk(32, 8);
    const int MR = B_ * NTOK;   // 32768
    const int YR = B_ * MTOK;   // 4096

    // [0] qkv weight transpose, [1] x conv, [2] y conv
    conv_w_t<<<dim3(3 * DMODEL / 32, DMODEL / 32), wblk>>>(w_qkv, p_wh + W_QKV, 3 * DMODEL);
    conv_h<<<(MR * DMODEL / 4 + 255) / 256, blk>>>(x, p_ah, MR * DMODEL / 4);
    conv_h<<<(YR * DMODEL / 4 + 255) / 256, blk>>>(y, p_yh, YR * DMODEL / 4);

    // [3] QKV GEMM (ncu capture target) with fused q/k RMSNorm+ReLU
    gemm_mma_h<<<dim3(3 * DMODEL / BN, MR / BM), blk, GEMM_SMEM>>>(
        p_ah, p_wh + W_QKV, b_qkv, p_qkv, 3 * DMODEL, 2048, qn_w, kn_w);

    // [4] ckv weight transpose, [5] CKV GEMM with fused c_k RMSNorm+ReLU
    conv_w_t<<<dim3(2 * DMODEL / 32, DMODEL / 32), wblk>>>(w_ckv, p_wh + W_CKV, 2 * DMODEL);
    gemm_mma_h<<<dim3(2 * DMODEL / BN, YR / BM), blk, GEMM_SMEM>>>(
        p_yh, p_wh + W_CKV, b_ckv, p_ckv, 2 * DMODEL, 1024, ckn_w, ckn_w);

    // [6] out weight transpose
    conv_w_t<<<dim3(DMODEL / 32, DMODEL / 32), wblk>>>(w_out, p_wh + W_OUT, DMODEL);

    // [7..8] kv + k_sum
    kv_accum<<<dim3(NCHUNK, 64), blk>>>(p_qkv, p_ckv, p_kvp, p_ksp);
    kv_reduce<<<(64 * DH * DH + 255) / 256, blk>>>(p_kvp, p_ksp, p_kv, p_ksum);

    // [9] attn (writes fp16 directly into x-side buffer)
    attn_apply<<<dim3(NTOK / 64, 64), blk>>>(p_qkv, p_kv, p_ksum, p_ah);

    // [10] output GEMM (fp32 direct-store epilogue)
    gemm_mma_f<<<dim3(DMODEL / BN, MR / BM), blk, GEMM_SMEM>>>(
        p_ah, p_wh + W_OUT, b_out, out, DMODEL);
}